// round 7
// baseline (speedup 1.0000x reference)
#include <cuda_runtime.h>
#include <cuda_bf16.h>
#include <math.h>
#include <cstdint>

// Problem constants
#define BATCH   2
#define SEQ     2048
#define DMODEL  1024
#define NHEADS  16
#define DK      64
#define MROWS   (BATCH * SEQ)      // 4096

// ---------------------------------------------------------------------------
// Scratch (device globals — no allocation allowed)
// ---------------------------------------------------------------------------
__device__ float g_q[MROWS * DMODEL];     // Q proj (pre-scaled, tf32-rounded)
__device__ float g_k[MROWS * DMODEL];     // K proj (tf32-rounded)
__device__ float g_v[MROWS * DMODEL];     // V proj (tf32-rounded)
__device__ float g_ctx[MROWS * DMODEL];   // attention output (tf32-rounded)
__device__ float r_q[MROWS * DMODEL];     // rounded inputs
__device__ float r_k[MROWS * DMODEL];
__device__ float r_v[MROWS * DMODEL];
__device__ float r_wq[DMODEL * DMODEL];   // rounded (and for wq: pre-scaled) weights
__device__ float r_wk[DMODEL * DMODEL];
__device__ float r_wv[DMODEL * DMODEL];
__device__ float r_wo[DMODEL * DMODEL];
__device__ float r_bq[DMODEL];            // scaled bias for Q path

__device__ __forceinline__ uint32_t f2tf32(float f) {
    uint32_t u;
    asm("cvt.rna.tf32.f32 %0, %1;" : "=r"(u) : "f"(f));
    return u;
}

// mma.sync m16n8k8 tf32 (layouts validated R4/R5).
__device__ __forceinline__ void mma_tf32(float* d, const uint32_t* a, const uint32_t* b) {
    asm volatile(
        "mma.sync.aligned.m16n8k8.row.col.f32.tf32.tf32.f32 "
        "{%0,%1,%2,%3}, {%4,%5,%6,%7}, {%8,%9}, {%0,%1,%2,%3};"
        : "+f"(d[0]), "+f"(d[1]), "+f"(d[2]), "+f"(d[3])
        : "r"(a[0]), "r"(a[1]), "r"(a[2]), "r"(a[3]),
          "r"(b[0]), "r"(b[1]));
}

// Fast exp2 for x <= 0: fixed-latency pipes only (no MUFU).
__device__ __forceinline__ float fexp2(float x) {
    x = fmaxf(x, -126.0f);
    float t = __fadd_rn(x, 12582912.0f);       // 1.5 * 2^23
    float u = __fsub_rn(t, 12582912.0f);       // round(x)
    float f = __fsub_rn(x, u);                 // [-0.5, 0.5]
    float p = 1.3333558e-3f;
    p = fmaf(p, f, 9.6181291e-3f);
    p = fmaf(p, f, 5.5504109e-2f);
    p = fmaf(p, f, 2.4022651e-1f);
    p = fmaf(p, f, 6.9314718e-1f);
    p = fmaf(p, f, 1.0f);
    float s = __int_as_float((__float_as_int(t) << 23) + 0x3F800000);
    return p * s;
}

// ---------------------------------------------------------------------------
// Prepass: dst = tf32_round(src * scale), vectorized.
// ---------------------------------------------------------------------------
__global__ void round_k(const float* __restrict__ src, float* __restrict__ dst,
                        float scale, int n4) {
    int i = blockIdx.x * blockDim.x + threadIdx.x;
    if (i < n4) {
        float4 v = ((const float4*)src)[i];
        uint4 o = make_uint4(f2tf32(v.x * scale), f2tf32(v.y * scale),
                             f2tf32(v.z * scale), f2tf32(v.w * scale));
        ((uint4*)dst)[i] = o;
    }
}

// ---------------------------------------------------------------------------
// GEMM body (mma.sync tf32): C = A[M,K] @ W[N,K]^T + bias.
// Inputs are PRE-ROUNDED to tf32 -> raw loads, no cvt in loop (HMMA tf32
// truncation is identity on pre-rounded data).
// Register-prefetch pipeline hides LDG latency under MMA compute.
// RoundOut: epilogue rounds C to tf32 (for tensors consumed by later MMAs).
// ---------------------------------------------------------------------------
#define GBK  16
#define ASTR 136

template <bool RoundOut>
__device__ __forceinline__ void gemm_body(const float* __restrict__ A,
                                          const float* __restrict__ W,
                                          const float* __restrict__ bias,
                                          float* __restrict__ C) {
    __shared__ uint32_t As[GBK][ASTR];
    __shared__ uint32_t Bs[GBK][ASTR];

    const int tid  = threadIdx.x;
    const int lane = tid & 31;
    const int wid  = tid >> 5;
    const int g    = lane >> 2;
    const int t    = lane & 3;
    const int wr   = wid >> 2;
    const int wc   = wid & 3;
    const int bx   = blockIdx.x;
    const int by   = blockIdx.y;

    const int lrow = tid >> 1;
    const int lk   = (tid & 1) * 8;

    const float* Ag = A + (size_t)(by * 128 + lrow) * DMODEL + lk;
    const float* Wg = W + (size_t)(bx * 128 + lrow) * DMODEL + lk;

    float acc[4][4][4];
    #pragma unroll
    for (int mi = 0; mi < 4; mi++)
        #pragma unroll
        for (int ni = 0; ni < 4; ni++)
            #pragma unroll
            for (int r = 0; r < 4; r++) acc[mi][ni][r] = 0.0f;

    uint4 pa0 = *(const uint4*)(Ag);
    uint4 pa1 = *(const uint4*)(Ag + 4);
    uint4 pb0 = *(const uint4*)(Wg);
    uint4 pb1 = *(const uint4*)(Wg + 4);

    for (int k0 = 0; k0 < DMODEL; k0 += GBK) {
        __syncthreads();   // previous tile's compute done
        As[lk + 0][lrow] = pa0.x; As[lk + 1][lrow] = pa0.y;
        As[lk + 2][lrow] = pa0.z; As[lk + 3][lrow] = pa0.w;
        As[lk + 4][lrow] = pa1.x; As[lk + 5][lrow] = pa1.y;
        As[lk + 6][lrow] = pa1.z; As[lk + 7][lrow] = pa1.w;
        Bs[lk + 0][lrow] = pb0.x; Bs[lk + 1][lrow] = pb0.y;
        Bs[lk + 2][lrow] = pb0.z; Bs[lk + 3][lrow] = pb0.w;
        Bs[lk + 4][lrow] = pb1.x; Bs[lk + 5][lrow] = pb1.y;
        Bs[lk + 6][lrow] = pb1.z; Bs[lk + 7][lrow] = pb1.w;
        __syncthreads();

        if (k0 + GBK < DMODEL) {   // prefetch next tile; overlaps MMAs below
            pa0 = *(const uint4*)(Ag + k0 + GBK);
            pa1 = *(const uint4*)(Ag + k0 + GBK + 4);
            pb0 = *(const uint4*)(Wg + k0 + GBK);
            pb1 = *(const uint4*)(Wg + k0 + GBK + 4);
        }

        #pragma unroll
        for (int ks = 0; ks < GBK; ks += 8) {
            uint32_t afr[4][4];
            #pragma unroll
            for (int mi = 0; mi < 4; mi++) {
                const int rb = wr * 64 + mi * 16 + g;
                afr[mi][0] = As[ks + t    ][rb];
                afr[mi][1] = As[ks + t    ][rb + 8];
                afr[mi][2] = As[ks + t + 4][rb];
                afr[mi][3] = As[ks + t + 4][rb + 8];
            }
            uint32_t bfr[4][2];
            #pragma unroll
            for (int ni = 0; ni < 4; ni++) {
                const int cb = wc * 32 + ni * 8 + g;
                bfr[ni][0] = Bs[ks + t    ][cb];
                bfr[ni][1] = Bs[ks + t + 4][cb];
            }
            #pragma unroll
            for (int mi = 0; mi < 4; mi++)
                #pragma unroll
                for (int ni = 0; ni < 4; ni++)
                    mma_tf32(acc[mi][ni], afr[mi], bfr[ni]);
        }
    }

    #pragma unroll
    for (int mi = 0; mi < 4; mi++) {
        const int r0 = by * 128 + wr * 64 + mi * 16 + g;
        #pragma unroll
        for (int ni = 0; ni < 4; ni++) {
            const int cc = bx * 128 + wc * 32 + ni * 8 + 2 * t;
            float2 bv = *(const float2*)(bias + cc);
            float v00 = acc[mi][ni][0] + bv.x, v01 = acc[mi][ni][1] + bv.y;
            float v10 = acc[mi][ni][2] + bv.x, v11 = acc[mi][ni][3] + bv.y;
            if (RoundOut) {
                *(uint2*)(C + (size_t)r0 * DMODEL + cc) =
                    make_uint2(f2tf32(v00), f2tf32(v01));
                *(uint2*)(C + (size_t)(r0 + 8) * DMODEL + cc) =
                    make_uint2(f2tf32(v10), f2tf32(v11));
            } else {
                *(float2*)(C + (size_t)r0 * DMODEL + cc)       = make_float2(v00, v01);
                *(float2*)(C + (size_t)(r0 + 8) * DMODEL + cc) = make_float2(v10, v11);
            }
        }
    }
}

__global__ __launch_bounds__(256, 2)
void qkv_gemm(const float* q, const float* k, const float* v,
              const float* wq, const float* wk, const float* wv,
              const float* bq, const float* bk, const float* bv,
              float* oq, float* ok, float* ov) {
    const float *A, *W, *B;
    float* C;
    if (blockIdx.z == 0)      { A = q; W = wq; B = bq; C = oq; }
    else if (blockIdx.z == 1) { A = k; W = wk; B = bk; C = ok; }
    else                      { A = v; W = wv; B = bv; C = ov; }
    gemm_body<true>(A, W, B, C);
}

__global__ __launch_bounds__(256, 2)
void out_gemm(const float* __restrict__ A, const float* __restrict__ W,
              const float* __restrict__ bias, float* __restrict__ C) {
    gemm_body<false>(A, W, bias, C);
}

// ---------------------------------------------------------------------------
// Flash attention, mma.sync tf32, FFMA softmax.
// Q/K/V arrive PRE-ROUNDED (Q also pre-scaled by 0.125*log2e via w_q) ->
// raw smem copies, zero cvt in the mainloop (P keeps RNA cvt).
// K/V register prefetch overlaps the next tile's LDG with softmax+PV.
// P staging is warp-private -> __syncwarp instead of __syncthreads.
// ---------------------------------------------------------------------------
#define FQT   128
#define FKT   64
#define QSTR  68
#define KSTR  68
#define VSTR  72
#define PSTR  68
#define SM_Q  0
#define SM_K  (FQT * QSTR)
#define SM_V  (SM_K + FKT * KSTR)
#define SM_P  (SM_V + FKT * VSTR)
#define ATT_SMEM ((SM_P + FQT * PSTR) * 4)

__global__ __launch_bounds__(256, 1)
void flash_attn_mma(const float* __restrict__ Q,
                    const float* __restrict__ Km,
                    const float* __restrict__ Vm,
                    float* __restrict__ ctx) {
    extern __shared__ uint32_t smf[];
    uint32_t* Qs = smf + SM_Q;
    uint32_t* Ks = smf + SM_K;
    uint32_t* Vs = smf + SM_V;
    uint32_t* Ps = smf + SM_P;

    const int tid  = threadIdx.x;
    const int lane = tid & 31;
    const int wid  = tid >> 5;
    const int g    = lane >> 2;
    const int t    = lane & 3;
    const int qb   = wid * 16;
    const int qt   = blockIdx.x;
    const int bh   = blockIdx.y;
    const int b    = bh >> 4;
    const int h    = bh & 15;

    // ---- Load Q tile (already scaled+rounded) ----
    {
        const int r  = tid >> 1;
        const int c0 = (tid & 1) * 32;
        const float* Qg = Q + (size_t)(b * SEQ + qt * FQT + r) * DMODEL + h * DK + c0;
        #pragma unroll
        for (int j = 0; j < 8; j++)
            *(uint4*)(Qs + r * QSTR + c0 + j * 4) = *(const uint4*)(Qg + j * 4);
    }

    float oacc[8][4];
    #pragma unroll
    for (int ni = 0; ni < 8; ni++)
        #pragma unroll
        for (int r = 0; r < 4; r++) oacc[ni][r] = 0.0f;
    float m0 = -1e30f, m1 = -1e30f, l0 = 0.0f, l1 = 0.0f;

    const int kvr = tid >> 2;
    const int kvc = (tid & 3) * 16;
    const float* Kg0 = Km + (size_t)(b * SEQ + kvr) * DMODEL + h * DK + kvc;
    const float* Vg0 = Vm + (size_t)(b * SEQ + kvr) * DMODEL + h * DK + kvc;

    uint4 kr[4], vr[4];
    #pragma unroll
    for (int j = 0; j < 4; j++) {
        kr[j] = *(const uint4*)(Kg0 + j * 4);
        vr[j] = *(const uint4*)(Vg0 + j * 4);
    }

    for (int kt = 0; kt < SEQ / FKT; kt++) {
        __syncthreads();   // all warps done reading Ks/Vs of previous tile

        #pragma unroll
        for (int j = 0; j < 4; j++) {
            *(uint4*)(Ks + kvr * KSTR + kvc + j * 4) = kr[j];
            *(uint4*)(Vs + kvr * VSTR + kvc + j * 4) = vr[j];
        }
        __syncthreads();

        // ---- S = Q K^T (log2 domain) ----
        float s[8][4];
        #pragma unroll
        for (int ni = 0; ni < 8; ni++)
            #pragma unroll
            for (int r = 0; r < 4; r++) s[ni][r] = 0.0f;

        #pragma unroll
        for (int ks = 0; ks < 8; ks++) {
            const int kc = ks * 8 + t;
            uint32_t a[4];
            a[0] = Qs[(qb + g    ) * QSTR + kc];
            a[1] = Qs[(qb + g + 8) * QSTR + kc];
            a[2] = Qs[(qb + g    ) * QSTR + kc + 4];
            a[3] = Qs[(qb + g + 8) * QSTR + kc + 4];
            #pragma unroll
            for (int ni = 0; ni < 8; ni++) {
                uint32_t bb[2];
                bb[0] = Ks[(ni * 8 + g) * KSTR + kc];
                bb[1] = Ks[(ni * 8 + g) * KSTR + kc + 4];
                mma_tf32(s[ni], a, bb);
            }
        }

        // prefetch next K/V tile — overlaps softmax + PV below
        if (kt + 1 < SEQ / FKT) {
            const float* Kg = Kg0 + (size_t)(kt + 1) * FKT * DMODEL;
            const float* Vg = Vg0 + (size_t)(kt + 1) * FKT * DMODEL;
            #pragma unroll
            for (int j = 0; j < 4; j++) {
                kr[j] = *(const uint4*)(Kg + j * 4);
                vr[j] = *(const uint4*)(Vg + j * 4);
            }
        }

        // ---- Online softmax (reduce over 4-lane t-group) ----
        float tm0 = -1e30f, tm1 = -1e30f;
        #pragma unroll
        for (int ni = 0; ni < 8; ni++) {
            tm0 = fmaxf(tm0, fmaxf(s[ni][0], s[ni][1]));
            tm1 = fmaxf(tm1, fmaxf(s[ni][2], s[ni][3]));
        }
        tm0 = fmaxf(tm0, __shfl_xor_sync(0xffffffffu, tm0, 1));
        tm0 = fmaxf(tm0, __shfl_xor_sync(0xffffffffu, tm0, 2));
        tm1 = fmaxf(tm1, __shfl_xor_sync(0xffffffffu, tm1, 1));
        tm1 = fmaxf(tm1, __shfl_xor_sync(0xffffffffu, tm1, 2));

        const float mn0 = fmaxf(m0, tm0);
        const float mn1 = fmaxf(m1, tm1);
        const float c0 = fexp2(m0 - mn0);
        const float c1 = fexp2(m1 - mn1);
        m0 = mn0; m1 = mn1;

        float rs0 = 0.0f, rs1 = 0.0f;
        #pragma unroll
        for (int ni = 0; ni < 8; ni++) {
            float p0 = fexp2(s[ni][0] - mn0);
            float p1 = fexp2(s[ni][1] - mn0);
            float p2 = fexp2(s[ni][2] - mn1);
            float p3 = fexp2(s[ni][3] - mn1);
            rs0 += p0 + p1;
            rs1 += p2 + p3;
            const int cc = ni * 8 + 2 * t;
            *(uint2*)(Ps + (qb + g    ) * PSTR + cc) = make_uint2(f2tf32(p0), f2tf32(p1));
            *(uint2*)(Ps + (qb + g + 8) * PSTR + cc) = make_uint2(f2tf32(p2), f2tf32(p3));
        }
        rs0 += __shfl_xor_sync(0xffffffffu, rs0, 1);
        rs0 += __shfl_xor_sync(0xffffffffu, rs0, 2);
        rs1 += __shfl_xor_sync(0xffffffffu, rs1, 1);
        rs1 += __shfl_xor_sync(0xffffffffu, rs1, 2);
        l0 = l0 * c0 + rs0;
        l1 = l1 * c1 + rs1;

        #pragma unroll
        for (int ni = 0; ni < 8; ni++) {
            oacc[ni][0] *= c0; oacc[ni][1] *= c0;
            oacc[ni][2] *= c1; oacc[ni][3] *= c1;
        }
        __syncwarp();      // P rows are warp-private: warp-level st->ld ordering

        // ---- O += P V ----
        #pragma unroll
        for (int ks = 0; ks < 8; ks++) {
            const int kc = ks * 8 + t;
            uint32_t a[4];
            a[0] = Ps[(qb + g    ) * PSTR + kc];
            a[1] = Ps[(qb + g + 8) * PSTR + kc];
            a[2] = Ps[(qb + g    ) * PSTR + kc + 4];
            a[3] = Ps[(qb + g + 8) * PSTR + kc + 4];
            #pragma unroll
            for (int ni = 0; ni < 8; ni++) {
                uint32_t bb[2];
                bb[0] = Vs[(ks * 8 + t    ) * VSTR + ni * 8 + g];
                bb[1] = Vs[(ks * 8 + t + 4) * VSTR + ni * 8 + g];
                mma_tf32(oacc[ni], a, bb);
            }
        }
    }

    // ---- Normalize, round (consumed by out_gemm MMA), write ctx ----
    const float inv0 = 1.0f / l0;
    const float inv1 = 1.0f / l1;
    const int r0 = b * SEQ + qt * FQT + qb + g;
    #pragma unroll
    for (int ni = 0; ni < 8; ni++) {
        const int cc = h * DK + ni * 8 + 2 * t;
        *(uint2*)(ctx + (size_t)r0 * DMODEL + cc) =
            make_uint2(f2tf32(oacc[ni][0] * inv0), f2tf32(oacc[ni][1] * inv0));
        *(uint2*)(ctx + (size_t)(r0 + 8) * DMODEL + cc) =
            make_uint2(f2tf32(oacc[ni][2] * inv1), f2tf32(oacc[ni][3] * inv1));
    }
}

// ---------------------------------------------------------------------------
// Launch
// ---------------------------------------------------------------------------
extern "C" void kernel_launch(void* const* d_in, const int* in_sizes, int n_in,
                              void* d_out, int out_size) {
    const float* q   = (const float*)d_in[0];
    const float* k   = (const float*)d_in[1];
    const float* v   = (const float*)d_in[2];
    const float* w_q = (const float*)d_in[3];
    const float* w_k = (const float*)d_in[4];
    const float* w_v = (const float*)d_in[5];
    const float* w_o = (const float*)d_in[6];
    const float* b_q = (const float*)d_in[7];
    const float* b_k = (const float*)d_in[8];
    const float* b_v = (const float*)d_in[9];
    const float* b_o = (const float*)d_in[10];
    float* out = (float*)d_out;

    float *gq, *gk, *gv, *gctx;
    float *rq, *rk, *rv, *rwq, *rwk, *rwv, *rwo, *rbq;
    cudaGetSymbolAddress((void**)&gq,   g_q);
    cudaGetSymbolAddress((void**)&gk,   g_k);
    cudaGetSymbolAddress((void**)&gv,   g_v);
    cudaGetSymbolAddress((void**)&gctx, g_ctx);
    cudaGetSymbolAddress((void**)&rq,   r_q);
    cudaGetSymbolAddress((void**)&rk,   r_k);
    cudaGetSymbolAddress((void**)&rv,   r_v);
    cudaGetSymbolAddress((void**)&rwq,  r_wq);
    cudaGetSymbolAddress((void**)&rwk,  r_wk);
    cudaGetSymbolAddress((void**)&rwv,  r_wv);
    cudaGetSymbolAddress((void**)&rwo,  r_wo);
    cudaGetSymbolAddress((void**)&rbq,  r_bq);

    cudaFuncSetAttribute(flash_attn_mma, cudaFuncAttributeMaxDynamicSharedMemorySize, ATT_SMEM);

    const float SCLL2E = 0.125f * 1.44269504088896f;

    // Prepass: tf32-round inputs & weights (scale folded into Q path)
    const int n4_act = MROWS * DMODEL / 4;    // 1048576
    const int n4_w   = DMODEL * DMODEL / 4;   // 262144
    round_k<<<n4_act / 256, 256>>>(q, rq, 1.0f, n4_act);
    round_k<<<n4_act / 256, 256>>>(k, rk, 1.0f, n4_act);
    round_k<<<n4_act / 256, 256>>>(v, rv, 1.0f, n4_act);
    round_k<<<n4_w / 256, 256>>>(w_q, rwq, SCLL2E, n4_w);
    round_k<<<n4_w / 256, 256>>>(w_k, rwk, 1.0f, n4_w);
    round_k<<<n4_w / 256, 256>>>(w_v, rwv, 1.0f, n4_w);
    round_k<<<n4_w / 256, 256>>>(w_o, rwo, 1.0f, n4_w);
    round_k<<<1, 256>>>(b_q, rbq, SCLL2E, DMODEL / 4);

    dim3 gqkv(DMODEL / 128, MROWS / 128, 3);  // (8, 32, 3)
    qkv_gemm<<<gqkv, 256>>>(rq, rk, rv, rwq, rwk, rwv, rbq, b_k, b_v, gq, gk, gv);

    dim3 ag(SEQ / FQT, BATCH * NHEADS);       // (16, 32)
    flash_attn_mma<<<ag, 256, ATT_SMEM>>>(gq, gk, gv, gctx);

    dim3 gg(DMODEL / 128, MROWS / 128);       // (8, 32)
    out_gemm<<<gg, 256>>>(gctx, rwo, b_o, out);
}

// round 8
// speedup vs baseline: 1.0908x; 1.0908x over previous
#include <cuda_runtime.h>
#include <cuda_bf16.h>
#include <math.h>
#include <cstdint>

// Problem constants
#define BATCH   2
#define SEQ     2048
#define DMODEL  1024
#define NHEADS  16
#define DK      64
#define MROWS   (BATCH * SEQ)      // 4096

// ---------------------------------------------------------------------------
// Scratch (device globals — no allocation allowed)
// ---------------------------------------------------------------------------
__device__ float g_q[MROWS * DMODEL];     // Q proj (pre-scaled, tf32-rounded)
__device__ float g_k[MROWS * DMODEL];     // K proj (tf32-rounded)
__device__ float g_v[MROWS * DMODEL];     // V proj (tf32-rounded)
__device__ float g_ctx[MROWS * DMODEL];   // attention output (tf32-rounded)

__device__ __forceinline__ uint32_t f2tf32(float f) {
    uint32_t u;
    asm("cvt.rna.tf32.f32 %0, %1;" : "=r"(u) : "f"(f));
    return u;
}

// mma.sync m16n8k8 tf32 (layouts validated R4/R5):
//   A: a0=(g,t) a1=(g+8,t) a2=(g,t+4) a3=(g+8,t+4)     [g=lane>>2, t=lane&3]
//   B: b0=(k=t,n=g) b1=(k=t+4,n=g)
//   C: c0=(g,2t) c1=(g,2t+1) c2=(g+8,2t) c3=(g+8,2t+1)
__device__ __forceinline__ void mma_tf32(float* d, const uint32_t* a, const uint32_t* b) {
    asm volatile(
        "mma.sync.aligned.m16n8k8.row.col.f32.tf32.tf32.f32 "
        "{%0,%1,%2,%3}, {%4,%5,%6,%7}, {%8,%9}, {%0,%1,%2,%3};"
        : "+f"(d[0]), "+f"(d[1]), "+f"(d[2]), "+f"(d[3])
        : "r"(a[0]), "r"(a[1]), "r"(a[2]), "r"(a[3]),
          "r"(b[0]), "r"(b[1]));
}

// Fast exp2 for x <= 0: fixed-latency pipes only (no MUFU).
__device__ __forceinline__ float fexp2(float x) {
    x = fmaxf(x, -126.0f);
    float t = __fadd_rn(x, 12582912.0f);       // 1.5 * 2^23
    float u = __fsub_rn(t, 12582912.0f);       // round(x)
    float f = __fsub_rn(x, u);                 // [-0.5, 0.5]
    float p = 1.3333558e-3f;
    p = fmaf(p, f, 9.6181291e-3f);
    p = fmaf(p, f, 5.5504109e-2f);
    p = fmaf(p, f, 2.4022651e-1f);
    p = fmaf(p, f, 6.9314718e-1f);
    p = fmaf(p, f, 1.0f);
    float s = __int_as_float((__float_as_int(t) << 23) + 0x3F800000);
    return p * s;
}

// ---------------------------------------------------------------------------
// GEMM body (mma.sync tf32): C = (ascale*A)[M,K] @ W[N,K]^T + ascale*bias.
// cvt.rna at smem-store time (measured neutral vs pre-rounding, saves the
// prepass launches). Register prefetch hides next tile's LDG under MMAs.
// RoundOut: epilogue rounds C to tf32 (for tensors consumed by later MMAs).
// ---------------------------------------------------------------------------
#define GBK  16
#define ASTR 136

template <bool RoundOut>
__device__ __forceinline__ void gemm_body(const float* __restrict__ A,
                                          const float* __restrict__ W,
                                          const float* __restrict__ bias,
                                          float* __restrict__ C,
                                          float ascale) {
    __shared__ uint32_t As[GBK][ASTR];
    __shared__ uint32_t Bs[GBK][ASTR];

    const int tid  = threadIdx.x;
    const int lane = tid & 31;
    const int wid  = tid >> 5;
    const int g    = lane >> 2;
    const int t    = lane & 3;
    const int wr   = wid >> 2;
    const int wc   = wid & 3;
    const int bx   = blockIdx.x;
    const int by   = blockIdx.y;

    const int lrow = tid >> 1;
    const int lk   = (tid & 1) * 8;

    const float* Ag = A + (size_t)(by * 128 + lrow) * DMODEL + lk;
    const float* Wg = W + (size_t)(bx * 128 + lrow) * DMODEL + lk;

    float acc[4][4][4];
    #pragma unroll
    for (int mi = 0; mi < 4; mi++)
        #pragma unroll
        for (int ni = 0; ni < 4; ni++)
            #pragma unroll
            for (int r = 0; r < 4; r++) acc[mi][ni][r] = 0.0f;

    float4 pa0 = *(const float4*)(Ag);
    float4 pa1 = *(const float4*)(Ag + 4);
    float4 pb0 = *(const float4*)(Wg);
    float4 pb1 = *(const float4*)(Wg + 4);

    for (int k0 = 0; k0 < DMODEL; k0 += GBK) {
        __syncthreads();   // previous tile's compute done
        As[lk + 0][lrow] = f2tf32(pa0.x * ascale); As[lk + 1][lrow] = f2tf32(pa0.y * ascale);
        As[lk + 2][lrow] = f2tf32(pa0.z * ascale); As[lk + 3][lrow] = f2tf32(pa0.w * ascale);
        As[lk + 4][lrow] = f2tf32(pa1.x * ascale); As[lk + 5][lrow] = f2tf32(pa1.y * ascale);
        As[lk + 6][lrow] = f2tf32(pa1.z * ascale); As[lk + 7][lrow] = f2tf32(pa1.w * ascale);
        Bs[lk + 0][lrow] = f2tf32(pb0.x); Bs[lk + 1][lrow] = f2tf32(pb0.y);
        Bs[lk + 2][lrow] = f2tf32(pb0.z); Bs[lk + 3][lrow] = f2tf32(pb0.w);
        Bs[lk + 4][lrow] = f2tf32(pb1.x); Bs[lk + 5][lrow] = f2tf32(pb1.y);
        Bs[lk + 6][lrow] = f2tf32(pb1.z); Bs[lk + 7][lrow] = f2tf32(pb1.w);
        __syncthreads();

        if (k0 + GBK < DMODEL) {   // prefetch next tile; overlaps MMAs below
            pa0 = *(const float4*)(Ag + k0 + GBK);
            pa1 = *(const float4*)(Ag + k0 + GBK + 4);
            pb0 = *(const float4*)(Wg + k0 + GBK);
            pb1 = *(const float4*)(Wg + k0 + GBK + 4);
        }

        #pragma unroll
        for (int ks = 0; ks < GBK; ks += 8) {
            uint32_t afr[4][4];
            #pragma unroll
            for (int mi = 0; mi < 4; mi++) {
                const int rb = wr * 64 + mi * 16 + g;
                afr[mi][0] = As[ks + t    ][rb];
                afr[mi][1] = As[ks + t    ][rb + 8];
                afr[mi][2] = As[ks + t + 4][rb];
                afr[mi][3] = As[ks + t + 4][rb + 8];
            }
            uint32_t bfr[4][2];
            #pragma unroll
            for (int ni = 0; ni < 4; ni++) {
                const int cb = wc * 32 + ni * 8 + g;
                bfr[ni][0] = Bs[ks + t    ][cb];
                bfr[ni][1] = Bs[ks + t + 4][cb];
            }
            #pragma unroll
            for (int mi = 0; mi < 4; mi++)
                #pragma unroll
                for (int ni = 0; ni < 4; ni++)
                    mma_tf32(acc[mi][ni], afr[mi], bfr[ni]);
        }
    }

    #pragma unroll
    for (int mi = 0; mi < 4; mi++) {
        const int r0 = by * 128 + wr * 64 + mi * 16 + g;
        #pragma unroll
        for (int ni = 0; ni < 4; ni++) {
            const int cc = bx * 128 + wc * 32 + ni * 8 + 2 * t;
            float2 bv = *(const float2*)(bias + cc);
            const float bsx = bv.x * ascale, bsy = bv.y * ascale;
            float v00 = acc[mi][ni][0] + bsx, v01 = acc[mi][ni][1] + bsy;
            float v10 = acc[mi][ni][2] + bsx, v11 = acc[mi][ni][3] + bsy;
            if (RoundOut) {
                *(uint2*)(C + (size_t)r0 * DMODEL + cc) =
                    make_uint2(f2tf32(v00), f2tf32(v01));
                *(uint2*)(C + (size_t)(r0 + 8) * DMODEL + cc) =
                    make_uint2(f2tf32(v10), f2tf32(v11));
            } else {
                *(float2*)(C + (size_t)r0 * DMODEL + cc)       = make_float2(v00, v01);
                *(float2*)(C + (size_t)(r0 + 8) * DMODEL + cc) = make_float2(v10, v11);
            }
        }
    }
}

__global__ __launch_bounds__(256, 2)
void qkv_gemm(const float* q, const float* k, const float* v,
              const float* wq, const float* wk, const float* wv,
              const float* bq, const float* bk, const float* bv,
              float* oq, float* ok, float* ov, float qscale) {
    const float *A, *W, *B;
    float* C;
    float s;
    if (blockIdx.z == 0)      { A = q; W = wq; B = bq; C = oq; s = qscale; }
    else if (blockIdx.z == 1) { A = k; W = wk; B = bk; C = ok; s = 1.0f; }
    else                      { A = v; W = wv; B = bv; C = ov; s = 1.0f; }
    gemm_body<true>(A, W, B, C, s);
}

__global__ __launch_bounds__(256, 2)
void out_gemm(const float* __restrict__ A, const float* __restrict__ W,
              const float* __restrict__ bias, float* __restrict__ C) {
    gemm_body<false>(A, W, bias, C, 1.0f);
}

// ---------------------------------------------------------------------------
// Flash attention, mma.sync tf32, FFMA softmax.
// Q/K/V arrive tf32-rounded (Q pre-scaled by 0.125*log2e) from qkv_gemm ->
// raw smem copies, zero cvt in mainloop (P keeps RNA cvt for normalization
// match). K/V register prefetch; warp-private P staging -> __syncwarp.
// __launch_bounds__(256,2): 2 CTAs/SM (2 x 105.5KB smem fits 228KB carveout,
// regs capped at 128) doubles the latency-hiding warp pool.
// ---------------------------------------------------------------------------
#define FQT   128
#define FKT   64
#define QSTR  68
#define KSTR  68
#define VSTR  72
#define PSTR  68
#define SM_Q  0
#define SM_K  (FQT * QSTR)
#define SM_V  (SM_K + FKT * KSTR)
#define SM_P  (SM_V + FKT * VSTR)
#define ATT_SMEM ((SM_P + FQT * PSTR) * 4)   // 105472 bytes

__global__ __launch_bounds__(256, 2)
void flash_attn_mma(const float* __restrict__ Q,
                    const float* __restrict__ Km,
                    const float* __restrict__ Vm,
                    float* __restrict__ ctx) {
    extern __shared__ uint32_t smf[];
    uint32_t* Qs = smf + SM_Q;
    uint32_t* Ks = smf + SM_K;
    uint32_t* Vs = smf + SM_V;
    uint32_t* Ps = smf + SM_P;

    const int tid  = threadIdx.x;
    const int lane = tid & 31;
    const int wid  = tid >> 5;
    const int g    = lane >> 2;
    const int t    = lane & 3;
    const int qb   = wid * 16;
    const int qt   = blockIdx.x;
    const int bh   = blockIdx.y;
    const int b    = bh >> 4;
    const int h    = bh & 15;

    // ---- Load Q tile (already scaled+rounded) ----
    {
        const int r  = tid >> 1;
        const int c0 = (tid & 1) * 32;
        const float* Qg = Q + (size_t)(b * SEQ + qt * FQT + r) * DMODEL + h * DK + c0;
        #pragma unroll
        for (int j = 0; j < 8; j++)
            *(uint4*)(Qs + r * QSTR + c0 + j * 4) = *(const uint4*)(Qg + j * 4);
    }

    float oacc[8][4];
    #pragma unroll
    for (int ni = 0; ni < 8; ni++)
        #pragma unroll
        for (int r = 0; r < 4; r++) oacc[ni][r] = 0.0f;
    float m0 = -1e30f, m1 = -1e30f, l0 = 0.0f, l1 = 0.0f;

    const int kvr = tid >> 2;
    const int kvc = (tid & 3) * 16;
    const float* Kg0 = Km + (size_t)(b * SEQ + kvr) * DMODEL + h * DK + kvc;
    const float* Vg0 = Vm + (size_t)(b * SEQ + kvr) * DMODEL + h * DK + kvc;

    uint4 kr[4], vr[4];
    #pragma unroll
    for (int j = 0; j < 4; j++) {
        kr[j] = *(const uint4*)(Kg0 + j * 4);
        vr[j] = *(const uint4*)(Vg0 + j * 4);
    }

    for (int kt = 0; kt < SEQ / FKT; kt++) {
        __syncthreads();   // all warps done reading Ks/Vs of previous tile

        #pragma unroll
        for (int j = 0; j < 4; j++) {
            *(uint4*)(Ks + kvr * KSTR + kvc + j * 4) = kr[j];
            *(uint4*)(Vs + kvr * VSTR + kvc + j * 4) = vr[j];
        }
        __syncthreads();

        // ---- S = Q K^T (log2 domain) ----
        float s[8][4];
        #pragma unroll
        for (int ni = 0; ni < 8; ni++)
            #pragma unroll
            for (int r = 0; r < 4; r++) s[ni][r] = 0.0f;

        #pragma unroll
        for (int ks = 0; ks < 8; ks++) {
            const int kc = ks * 8 + t;
            uint32_t a[4];
            a[0] = Qs[(qb + g    ) * QSTR + kc];
            a[1] = Qs[(qb + g + 8) * QSTR + kc];
            a[2] = Qs[(qb + g    ) * QSTR + kc + 4];
            a[3] = Qs[(qb + g + 8) * QSTR + kc + 4];
            #pragma unroll
            for (int ni = 0; ni < 8; ni++) {
                uint32_t bb[2];
                bb[0] = Ks[(ni * 8 + g) * KSTR + kc];
                bb[1] = Ks[(ni * 8 + g) * KSTR + kc + 4];
                mma_tf32(s[ni], a, bb);
            }
        }

        // prefetch next K/V tile — overlaps softmax + PV below
        if (kt + 1 < SEQ / FKT) {
            const float* Kg = Kg0 + (size_t)(kt + 1) * FKT * DMODEL;
            const float* Vg = Vg0 + (size_t)(kt + 1) * FKT * DMODEL;
            #pragma unroll
            for (int j = 0; j < 4; j++) {
                kr[j] = *(const uint4*)(Kg + j * 4);
                vr[j] = *(const uint4*)(Vg + j * 4);
            }
        }

        // ---- Online softmax (reduce over 4-lane t-group) ----
        float tm0 = -1e30f, tm1 = -1e30f;
        #pragma unroll
        for (int ni = 0; ni < 8; ni++) {
            tm0 = fmaxf(tm0, fmaxf(s[ni][0], s[ni][1]));
            tm1 = fmaxf(tm1, fmaxf(s[ni][2], s[ni][3]));
        }
        tm0 = fmaxf(tm0, __shfl_xor_sync(0xffffffffu, tm0, 1));
        tm0 = fmaxf(tm0, __shfl_xor_sync(0xffffffffu, tm0, 2));
        tm1 = fmaxf(tm1, __shfl_xor_sync(0xffffffffu, tm1, 1));
        tm1 = fmaxf(tm1, __shfl_xor_sync(0xffffffffu, tm1, 2));

        const float mn0 = fmaxf(m0, tm0);
        const float mn1 = fmaxf(m1, tm1);
        const float c0 = fexp2(m0 - mn0);
        const float c1 = fexp2(m1 - mn1);
        m0 = mn0; m1 = mn1;

        float rs0 = 0.0f, rs1 = 0.0f;
        #pragma unroll
        for (int ni = 0; ni < 8; ni++) {
            float p0 = fexp2(s[ni][0] - mn0);
            float p1 = fexp2(s[ni][1] - mn0);
            float p2 = fexp2(s[ni][2] - mn1);
            float p3 = fexp2(s[ni][3] - mn1);
            rs0 += p0 + p1;
            rs1 += p2 + p3;
            const int cc = ni * 8 + 2 * t;
            *(uint2*)(Ps + (qb + g    ) * PSTR + cc) = make_uint2(f2tf32(p0), f2tf32(p1));
            *(uint2*)(Ps + (qb + g + 8) * PSTR + cc) = make_uint2(f2tf32(p2), f2tf32(p3));
        }
        rs0 += __shfl_xor_sync(0xffffffffu, rs0, 1);
        rs0 += __shfl_xor_sync(0xffffffffu, rs0, 2);
        rs1 += __shfl_xor_sync(0xffffffffu, rs1, 1);
        rs1 += __shfl_xor_sync(0xffffffffu, rs1, 2);
        l0 = l0 * c0 + rs0;
        l1 = l1 * c1 + rs1;

        #pragma unroll
        for (int ni = 0; ni < 8; ni++) {
            oacc[ni][0] *= c0; oacc[ni][1] *= c0;
            oacc[ni][2] *= c1; oacc[ni][3] *= c1;
        }
        __syncwarp();      // P rows are warp-private

        // ---- O += P V ----
        #pragma unroll
        for (int ks = 0; ks < 8; ks++) {
            const int kc = ks * 8 + t;
            uint32_t a[4];
            a[0] = Ps[(qb + g    ) * PSTR + kc];
            a[1] = Ps[(qb + g + 8) * PSTR + kc];
            a[2] = Ps[(qb + g    ) * PSTR + kc + 4];
            a[3] = Ps[(qb + g + 8) * PSTR + kc + 4];
            #pragma unroll
            for (int ni = 0; ni < 8; ni++) {
                uint32_t bb[2];
                bb[0] = Vs[(ks * 8 + t    ) * VSTR + ni * 8 + g];
                bb[1] = Vs[(ks * 8 + t + 4) * VSTR + ni * 8 + g];
                mma_tf32(oacc[ni], a, bb);
            }
        }
    }

    // ---- Normalize, round (consumed by out_gemm MMA), write ctx ----
    const float inv0 = 1.0f / l0;
    const float inv1 = 1.0f / l1;
    const int r0 = b * SEQ + qt * FQT + qb + g;
    #pragma unroll
    for (int ni = 0; ni < 8; ni++) {
        const int cc = h * DK + ni * 8 + 2 * t;
        *(uint2*)(ctx + (size_t)r0 * DMODEL + cc) =
            make_uint2(f2tf32(oacc[ni][0] * inv0), f2tf32(oacc[ni][1] * inv0));
        *(uint2*)(ctx + (size_t)(r0 + 8) * DMODEL + cc) =
            make_uint2(f2tf32(oacc[ni][2] * inv1), f2tf32(oacc[ni][3] * inv1));
    }
}

// ---------------------------------------------------------------------------
// Launch
// ---------------------------------------------------------------------------
extern "C" void kernel_launch(void* const* d_in, const int* in_sizes, int n_in,
                              void* d_out, int out_size) {
    const float* q   = (const float*)d_in[0];
    const float* k   = (const float*)d_in[1];
    const float* v   = (const float*)d_in[2];
    const float* w_q = (const float*)d_in[3];
    const float* w_k = (const float*)d_in[4];
    const float* w_v = (const float*)d_in[5];
    const float* w_o = (const float*)d_in[6];
    const float* b_q = (const float*)d_in[7];
    const float* b_k = (const float*)d_in[8];
    const float* b_v = (const float*)d_in[9];
    const float* b_o = (const float*)d_in[10];
    float* out = (float*)d_out;

    float *gq, *gk, *gv, *gctx;
    cudaGetSymbolAddress((void**)&gq,   g_q);
    cudaGetSymbolAddress((void**)&gk,   g_k);
    cudaGetSymbolAddress((void**)&gv,   g_v);
    cudaGetSymbolAddress((void**)&gctx, g_ctx);

    cudaFuncSetAttribute(flash_attn_mma, cudaFuncAttributeMaxDynamicSharedMemorySize, ATT_SMEM);

    const float SCLL2E = 0.125f * 1.44269504088896f;

    dim3 gqkv(DMODEL / 128, MROWS / 128, 3);  // (8, 32, 3)
    qkv_gemm<<<gqkv, 256>>>(q, k, v, w_q, w_k, w_v, b_q, b_k, b_v,
                            gq, gk, gv, SCLL2E);

    dim3 ag(SEQ / FQT, BATCH * NHEADS);       // (16, 32)
    flash_attn_mma<<<ag, 256, ATT_SMEM>>>(gq, gk, gv, gctx);

    dim3 gg(DMODEL / 128, MROWS / 128);       // (8, 32)
    out_gemm<<<gg, 256>>>(gctx, w_o, b_o, out);
}